// round 7
// baseline (speedup 1.0000x reference)
#include <cuda_runtime.h>
#include <cuda_fp16.h>
#include <cstdint>
#include <math.h>

// ---------------------------------------------------------------- dims
#define B_  16
#define C_  16
#define P_  512
#define D_  256
#define Z_  (B_*C_)            // 256 batches
#define BCPD (B_*C_*P_*D_)     // 33,554,432
#define BPD  (B_*P_*D_)        // 2,097,152
#define WELEM (C_*D_*D_)       // 1,048,576

// ---------------------------------------------------------------- scratch
__device__ half g_qry[BCPD];
__device__ half g_ctx[BCPD];
__device__ half g_q[BCPD];
__device__ half g_k[BCPD];
__device__ half g_vT[BCPD];
__device__ half g_wqT[WELEM], g_wkT[WELEM], g_wvT[WELEM];

// ---------------------------------------------------------------- helpers
__device__ __forceinline__ uint32_t smem_u32(const void* p) {
    uint32_t a;
    asm("{ .reg .u64 t; cvta.to.shared.u64 t, %1; cvt.u32.u64 %0, t; }" : "=r"(a) : "l"(p));
    return a;
}

#define CP16(saddr, gaddr) \
    asm volatile("cp.async.cg.shared.global [%0], [%1], 16;" :: "r"(saddr), "l"(gaddr) : "memory")
#define CP_COMMIT() asm volatile("cp.async.commit_group;" ::: "memory")
#define CP_WAIT1()  asm volatile("cp.async.wait_group 1;" ::: "memory")
#define CP_WAIT0()  asm volatile("cp.async.wait_group 0;" ::: "memory")

#define LDSM4(r0, r1, r2, r3, addr) \
    asm volatile("ldmatrix.sync.aligned.m8n8.x4.shared.b16 {%0,%1,%2,%3}, [%4];" \
        : "=r"(r0), "=r"(r1), "=r"(r2), "=r"(r3) : "r"(addr))

#define MMAH(c, a, b) \
    asm volatile("mma.sync.aligned.m16n8k16.row.col.f32.f16.f16.f32 " \
        "{%0,%1,%2,%3}, {%4,%5,%6,%7}, {%8,%9}, {%0,%1,%2,%3};" \
        : "+f"((c)[0]), "+f"((c)[1]), "+f"((c)[2]), "+f"((c)[3]) \
        : "r"((a)[0]), "r"((a)[1]), "r"((a)[2]), "r"((a)[3]), "r"((b)[0]), "r"((b)[1]))

__device__ __forceinline__ uint32_t packh2(float lo, float hi) {
    __half2 h = __floats2half2_rn(lo, hi);
    return *reinterpret_cast<uint32_t*>(&h);
}

// ---------------------------------------------------------------- proj GEMM smem
#define OFF_A    0
#define OFF_B    16384
#define STAGE_SZ 32768
#define SMEM_SZ  66560
#define STG_LD   130

// ---------------------------------------------------------------- proj GEMM
// D = A @ B^T, fp16 in, fp32 acc. CTA 128x128, K-chunk 64.
// OUT_MODE: 1 = fp16, 2 = fp16 transposed (Out[z][N][M]).
template<int OUT_MODE>
__global__ __launch_bounds__(256, 2)
void mma_gemm(const half* __restrict__ A, const half* __restrict__ B,
              const float* __restrict__ bias,
              half* __restrict__ OutH,
              int M, int N, int K, int bMask, float scale)
{
    extern __shared__ char smem[];
    const uint32_t sb = smem_u32(smem);

    const int t    = threadIdx.x;
    const int wid  = t >> 5;
    const int lane = t & 31;
    const int wr   = wid >> 2;
    const int wc   = wid & 3;

    const int z  = blockIdx.z;
    const int bz = z & bMask;
    const int m0 = blockIdx.y * 128;
    const int n0 = blockIdx.x * 128;

    const long Kb = (long)K * 2;
    const char* gA = (const char*)(A + ((long)z  * M + m0) * K);
    const char* gB = (const char*)(B + ((long)bz * N + n0) * K);

    uint32_t soffv[4]; long goffv[4];
#pragma unroll
    for (int i = 0; i < 4; i++) {
        int id = t + i * 256;
        int r = id >> 3, c = id & 7;
        soffv[i] = r * 128 + ((uint32_t)(c ^ (r & 7)) << 4);
        goffv[i] = (long)r * Kb + c * 16;
    }

    uint32_t roA[4]; int swA[4];
#pragma unroll
    for (int mi = 0; mi < 4; mi++) {
        int row = wr * 64 + mi * 16 + (lane & 15);
        roA[mi] = row * 128;
        swA[mi] = row & 7;
    }
    const int a_kc = lane >> 4;
    uint32_t roB[2]; int swB[2];
#pragma unroll
    for (int nj = 0; nj < 2; nj++) {
        int row = wc * 32 + nj * 16 + (lane & 7) + ((lane >> 4) << 3);
        roB[nj] = row * 128;
        swB[nj] = row & 7;
    }
    const int b_kc = (lane >> 3) & 1;

    float acc[4][4][4];
#pragma unroll
    for (int mi = 0; mi < 4; mi++)
#pragma unroll
        for (int ni = 0; ni < 4; ni++)
#pragma unroll
            for (int r = 0; r < 4; r++) acc[mi][ni][r] = 0.f;

    const int nch = K >> 6;

    auto load_chunk = [&](int ch, int buf) {
        const uint32_t s = sb + buf * STAGE_SZ;
        const long gk = (long)ch * 128;
#pragma unroll
        for (int i = 0; i < 4; i++) {
            CP16(s + OFF_A + soffv[i], gA + goffv[i] + gk);
            CP16(s + OFF_B + soffv[i], gB + goffv[i] + gk);
        }
        CP_COMMIT();
    };

    load_chunk(0, 0);

    for (int ch = 0; ch < nch; ch++) {
        const int buf = ch & 1;
        if (ch + 1 < nch) { load_chunk(ch + 1, (ch + 1) & 1); CP_WAIT1(); }
        else              { CP_WAIT0(); }
        __syncthreads();

        const uint32_t sA = sb + buf * STAGE_SZ + OFF_A;
        const uint32_t sB = sb + buf * STAGE_SZ + OFF_B;

#pragma unroll
        for (int ks = 0; ks < 4; ks++) {
            const int kcA = ks * 2 + a_kc;
            const int kcB = ks * 2 + b_kc;

            uint32_t a[4][4], b[4][2];
#pragma unroll
            for (int mi = 0; mi < 4; mi++)
                LDSM4(a[mi][0], a[mi][1], a[mi][2], a[mi][3],
                      sA + roA[mi] + ((uint32_t)(kcA ^ swA[mi]) << 4));
#pragma unroll
            for (int nj = 0; nj < 2; nj++)
                LDSM4(b[nj*2][0], b[nj*2][1], b[nj*2+1][0], b[nj*2+1][1],
                      sB + roB[nj] + ((uint32_t)(kcB ^ swB[nj]) << 4));
#pragma unroll
            for (int mi = 0; mi < 4; mi++)
#pragma unroll
                for (int ni = 0; ni < 4; ni++)
                    MMAH(acc[mi][ni], a[mi], b[ni]);
        }
        __syncthreads();
    }

    // epilogue via padded smem stage
    float* stg = reinterpret_cast<float*>(smem);
    {
        const int grp = lane >> 2;
        const int tq  = lane & 3;
#pragma unroll
        for (int mi = 0; mi < 4; mi++) {
            const int m = wr * 64 + mi * 16 + grp;
#pragma unroll
            for (int ni = 0; ni < 4; ni++) {
                const int n = wc * 32 + ni * 8 + 2 * tq;
                stg[m * STG_LD + n]           = acc[mi][ni][0];
                stg[m * STG_LD + n + 1]       = acc[mi][ni][1];
                stg[(m + 8) * STG_LD + n]     = acc[mi][ni][2];
                stg[(m + 8) * STG_LD + n + 1] = acc[mi][ni][3];
            }
        }
    }
    __syncthreads();

    const float* brow = bias + (long)bz * N + n0;

    if (OUT_MODE == 1) {
#pragma unroll
        for (int r = 0; r < 32; r++) {
            int idx = r * 256 + t;
            int m = idx >> 6, j = idx & 63;
            int n = 2 * j;
            float v0 = fmaxf(stg[m * STG_LD + n]     + brow[n],     0.f) * scale;
            float v1 = fmaxf(stg[m * STG_LD + n + 1] + brow[n + 1], 0.f) * scale;
            long base = ((long)z * M + m0 + m) * N + n0 + n;
            __half2 H; H.x = __float2half(v0); H.y = __float2half(v1);
            *reinterpret_cast<__half2*>(&OutH[base]) = H;
        }
    } else {   // OUT_MODE == 2: fp16 transposed Out[z][N][M]
#pragma unroll
        for (int r = 0; r < 32; r++) {
            int idx = r * 256 + t;
            int e = idx >> 6, j = idx & 63;
            int q = 2 * j;
            float bv = brow[e];
            float v0 = fmaxf(stg[q * STG_LD + e]       + bv, 0.f) * scale;
            float v1 = fmaxf(stg[(q + 1) * STG_LD + e] + bv, 0.f) * scale;
            long base = ((long)z * N + n0 + e) * M + m0 + q;
            __half2 H; H.x = __float2half(v0); H.y = __float2half(v1);
            *reinterpret_cast<__half2*>(&OutH[base]) = H;
        }
    }
}

// ---------------------------------------------------------------- fused attention
// out[z][p][e] = softmax_kv( q[z][p][:] . k[z][kv][:] ) @ v  with v given as
// vT[z][e][kv]. CTA: 256 thr / 8 warps; q-block 128 (16 rows per warp),
// kv-block 64, 8 iterations; online softmax; P kept in registers as A-frags.
#define A_OFQ   0
#define A_OFK0  65536
#define A_OFK1  98304
#define A_OFV0  131072
#define A_OFV1  163840
#define A_SMEM  196608

__global__ __launch_bounds__(256, 1)
void attn_fused(const half* __restrict__ Qm, const half* __restrict__ Km,
                const half* __restrict__ Vtm, float* __restrict__ Out)
{
    extern __shared__ char smem[];
    const uint32_t sb = smem_u32(smem);
    const int t = threadIdx.x;
    const int wid = t >> 5, lane = t & 31;
    const int z  = blockIdx.y;
    const int p0 = blockIdx.x * 128;

    const char* gQ = (const char*)(Qm  + ((long)z * P_ + p0) * D_);
    const char* gK = (const char*)(Km  + (long)z * P_ * D_);
    const char* gV = (const char*)(Vtm + (long)z * D_ * P_);

    // Q: 128 rows x 512B, swizzle (r&7)<<2 on 16B chunks
    {
#pragma unroll
        for (int i = 0; i < 16; i++) {
            int id = t + i * 256;
            int r = id >> 5, c = id & 31;
            CP16(sb + A_OFQ + r * 512 + ((uint32_t)(c ^ ((r & 7) << 2)) << 4),
                 gQ + (long)r * 512 + c * 16);
        }
    }
    auto loadK = [&](int j, uint32_t dst) {     // 64 rows x 512B
#pragma unroll
        for (int i = 0; i < 8; i++) {
            int id = t + i * 256;
            int r = id >> 5, c = id & 31;
            CP16(dst + r * 512 + ((uint32_t)(c ^ ((r & 7) << 2)) << 4),
                 gK + ((long)(j * 64 + r)) * 512 + c * 16);
        }
    };
    auto loadV = [&](int j, uint32_t dst) {     // 256 rows(e) x 128B (64 q)
#pragma unroll
        for (int i = 0; i < 8; i++) {
            int id = t + i * 256;
            int r = id >> 3, c = id & 7;
            CP16(dst + r * 128 + ((uint32_t)(c ^ (r & 7)) << 4),
                 gV + (long)r * 1024 + j * 128 + c * 16);
        }
    };
    loadK(0, sb + A_OFK0);
    loadV(0, sb + A_OFV0);
    CP_COMMIT();

    const int grp = lane >> 2, tq = lane & 3;
    const int aRow = wid * 16 + (lane & 15);
    const uint32_t aRO = aRow * 512;
    const uint32_t aSW = (uint32_t)(aRow & 7) << 2;
    const int a_kc = lane >> 4;
    const int bRowB = (lane & 7) + ((lane >> 4) << 3);
    const int b_kc  = (lane >> 3) & 1;
    const uint32_t vSW = (uint32_t)(lane & 7);

    float accO[32][4];
#pragma unroll
    for (int ni = 0; ni < 32; ni++)
#pragma unroll
        for (int r = 0; r < 4; r++) accO[ni][r] = 0.f;
    float mrow0 = -1e30f, mrow1 = -1e30f, lrow0 = 0.f, lrow1 = 0.f;

    for (int j = 0; j < 8; j++) {
        const uint32_t sK = sb + ((j & 1) ? A_OFK1 : A_OFK0);
        const uint32_t sV = sb + ((j & 1) ? A_OFV1 : A_OFV0);
        if (j < 7) {
            loadK(j + 1, sb + (((j + 1) & 1) ? A_OFK1 : A_OFK0));
            loadV(j + 1, sb + (((j + 1) & 1) ? A_OFV1 : A_OFV0));
            CP_COMMIT();
            CP_WAIT1();
        } else {
            CP_WAIT0();
        }
        __syncthreads();

        // ---- S = Q @ K_j^T : warp tile 16 x 64
        float accS[8][4];
#pragma unroll
        for (int ni = 0; ni < 8; ni++)
#pragma unroll
            for (int r = 0; r < 4; r++) accS[ni][r] = 0.f;

#pragma unroll
        for (int ks = 0; ks < 16; ks++) {
            uint32_t a[4];
            LDSM4(a[0], a[1], a[2], a[3],
                  sb + A_OFQ + aRO + ((uint32_t)((ks * 2 + a_kc) ^ aSW) << 4));
            uint32_t bf[4][4];
#pragma unroll
            for (int nj = 0; nj < 4; nj++) {
                int n = nj * 16 + bRowB;
                LDSM4(bf[nj][0], bf[nj][1], bf[nj][2], bf[nj][3],
                      sK + n * 512 + ((uint32_t)((ks * 2 + b_kc) ^ ((n & 7) << 2)) << 4));
            }
#pragma unroll
            for (int nj = 0; nj < 4; nj++) {
                MMAH(accS[2 * nj],     a, (&bf[nj][0]));
                MMAH(accS[2 * nj + 1], a, (&bf[nj][2]));
            }
        }

        // ---- online softmax (rows grp and grp+8 of this warp's 16)
        float rmax0 = -1e30f, rmax1 = -1e30f;
#pragma unroll
        for (int ni = 0; ni < 8; ni++) {
            rmax0 = fmaxf(rmax0, fmaxf(accS[ni][0], accS[ni][1]));
            rmax1 = fmaxf(rmax1, fmaxf(accS[ni][2], accS[ni][3]));
        }
        rmax0 = fmaxf(rmax0, __shfl_xor_sync(0xffffffffu, rmax0, 1));
        rmax0 = fmaxf(rmax0, __shfl_xor_sync(0xffffffffu, rmax0, 2));
        rmax1 = fmaxf(rmax1, __shfl_xor_sync(0xffffffffu, rmax1, 1));
        rmax1 = fmaxf(rmax1, __shfl_xor_sync(0xffffffffu, rmax1, 2));

        const float mn0 = fmaxf(mrow0, rmax0);
        const float mn1 = fmaxf(mrow1, rmax1);
        const float sc0 = __expf(mrow0 - mn0);
        const float sc1 = __expf(mrow1 - mn1);
        mrow0 = mn0; mrow1 = mn1;

        float rs0 = 0.f, rs1 = 0.f;
#pragma unroll
        for (int ni = 0; ni < 8; ni++) {
            accS[ni][0] = __expf(accS[ni][0] - mn0);
            accS[ni][1] = __expf(accS[ni][1] - mn0);
            accS[ni][2] = __expf(accS[ni][2] - mn1);
            accS[ni][3] = __expf(accS[ni][3] - mn1);
            rs0 += accS[ni][0] + accS[ni][1];
            rs1 += accS[ni][2] + accS[ni][3];
        }
        rs0 += __shfl_xor_sync(0xffffffffu, rs0, 1);
        rs0 += __shfl_xor_sync(0xffffffffu, rs0, 2);
        rs1 += __shfl_xor_sync(0xffffffffu, rs1, 1);
        rs1 += __shfl_xor_sync(0xffffffffu, rs1, 2);
        lrow0 = lrow0 * sc0 + rs0;
        lrow1 = lrow1 * sc1 + rs1;

#pragma unroll
        for (int ni = 0; ni < 32; ni++) {
            accO[ni][0] *= sc0; accO[ni][1] *= sc0;
            accO[ni][2] *= sc1; accO[ni][3] *= sc1;
        }

        // P as A-fragments (C-frag layout == A-frag layout)
        uint32_t pa[4][4];
#pragma unroll
        for (int kk = 0; kk < 4; kk++) {
            pa[kk][0] = packh2(accS[2 * kk][0],     accS[2 * kk][1]);
            pa[kk][1] = packh2(accS[2 * kk][2],     accS[2 * kk][3]);
            pa[kk][2] = packh2(accS[2 * kk + 1][0], accS[2 * kk + 1][1]);
            pa[kk][3] = packh2(accS[2 * kk + 1][2], accS[2 * kk + 1][3]);
        }

        // ---- O += P @ V_j : warp tile 16 x 256
#pragma unroll
        for (int ng = 0; ng < 8; ng++) {
            uint32_t bb[4][8];
            const int n1 = ng * 32 + bRowB;
            const int n2 = n1 + 16;
#pragma unroll
            for (int kk = 0; kk < 4; kk++) {
                const uint32_t kc = (uint32_t)(kk * 2 + b_kc);
                LDSM4(bb[kk][0], bb[kk][1], bb[kk][2], bb[kk][3],
                      sV + n1 * 128 + ((kc ^ vSW) << 4));
                LDSM4(bb[kk][4], bb[kk][5], bb[kk][6], bb[kk][7],
                      sV + n2 * 128 + ((kc ^ vSW) << 4));
            }
#pragma unroll
            for (int kk = 0; kk < 4; kk++) {
                MMAH(accO[ng * 4 + 0], pa[kk], (&bb[kk][0]));
                MMAH(accO[ng * 4 + 1], pa[kk], (&bb[kk][2]));
                MMAH(accO[ng * 4 + 2], pa[kk], (&bb[kk][4]));
                MMAH(accO[ng * 4 + 3], pa[kk], (&bb[kk][6]));
            }
        }
        __syncthreads();
    }

    // ---- epilogue: normalize and store fp32
    const float inv0 = 1.f / lrow0;
    const float inv1 = 1.f / lrow1;
    const int rowp = p0 + wid * 16 + grp;
    const long base0 = ((long)z * P_ + rowp) * D_;
    const long base1 = base0 + 8 * D_;
#pragma unroll
    for (int ni = 0; ni < 32; ni++) {
        const int col = ni * 8 + 2 * tq;
        float2 v0; v0.x = accO[ni][0] * inv0; v0.y = accO[ni][1] * inv0;
        float2 v1; v1.x = accO[ni][2] * inv1; v1.y = accO[ni][3] * inv1;
        *reinterpret_cast<float2*>(&Out[base0 + col]) = v0;
        *reinterpret_cast<float2*>(&Out[base1 + col]) = v1;
    }
}

// ---------------------------------------------------------------- elementwise
__global__ __launch_bounds__(256) void ctx_qry_kernel(
        const float* __restrict__ q, const float* __restrict__ aw,
        half* __restrict__ qry16, half* __restrict__ ctx16)
{
    int idx = blockIdx.x * 256 + threadIdx.x;      // over BPD/2
    if (idx >= BPD / 2) return;
    int dp = idx & 127;
    int p  = (idx >> 7) & 511;
    int b  = idx >> 16;

    float2 qv[C_], pr[C_];
    float2 accv = make_float2(0.f, 0.f);
#pragma unroll
    for (int c = 0; c < C_; c++) {
        long qo = ((long)((b * C_ + c) * P_ + p)) * D_ + 2 * dp;
        long ao = ((long)(c * P_ + p)) * D_ + 2 * dp;
        float2 qq = *reinterpret_cast<const float2*>(&q[qo]);
        float2 w  = *reinterpret_cast<const float2*>(&aw[ao]);
        qv[c] = qq;
        pr[c].x = w.x * qq.x; pr[c].y = w.y * qq.y;
        accv.x += pr[c].x;    accv.y += pr[c].y;
    }
#pragma unroll
    for (int c = 0; c < C_; c++) {
        long o = ((long)((b * C_ + c) * P_ + p)) * D_ + 2 * dp;
        __half2 Cv; Cv.x = __float2half(accv.x - pr[c].x);
        Cv.y = __float2half(accv.y - pr[c].y);
        *reinterpret_cast<__half2*>(&ctx16[o]) = Cv;
        __half2 Qv; Qv.x = __float2half(qv[c].x);
        Qv.y = __float2half(qv[c].y);
        *reinterpret_cast<__half2*>(&qry16[o]) = Qv;
    }
}

__global__ __launch_bounds__(256) void split_wT_kernel(const float* __restrict__ w,
                                                       half* __restrict__ wT)
{
    __shared__ float s[32][33];
    int bc = blockIdx.x >> 6;
    int t6 = blockIdx.x & 63;
    int e0 = (t6 >> 3) * 32, d0 = (t6 & 7) * 32;
    int tx = threadIdx.x & 31, ty = threadIdx.x >> 5;
#pragma unroll
    for (int r = 0; r < 4; r++) {
        int row = ty + r * 8;
        s[row][tx] = w[((long)bc * 256 + d0 + row) * 256 + e0 + tx];
    }
    __syncthreads();
#pragma unroll
    for (int r = 0; r < 4; r++) {
        int row = ty + r * 8;
        wT[((long)bc * 256 + e0 + row) * 256 + d0 + tx] = __float2half(s[tx][row]);
    }
}

// ---------------------------------------------------------------- launcher
extern "C" void kernel_launch(void* const* d_in, const int* in_sizes, int n_in,
                              void* d_out, int out_size)
{
    const float* query = (const float*)d_in[0];
    const float* aw    = (const float*)d_in[1];
    const float* qw    = (const float*)d_in[2];
    const float* kw    = (const float*)d_in[3];
    const float* vw    = (const float*)d_in[4];
    const float* qb    = (const float*)d_in[5];
    const float* kb    = (const float*)d_in[6];
    const float* vb    = (const float*)d_in[7];
    float* out = (float*)d_out;

    half *qry16, *ctx16, *qB, *kB, *vT;
    half *wqT, *wkT, *wvT;
    cudaGetSymbolAddress((void**)&qry16, g_qry);
    cudaGetSymbolAddress((void**)&ctx16, g_ctx);
    cudaGetSymbolAddress((void**)&qB, g_q);
    cudaGetSymbolAddress((void**)&kB, g_k);
    cudaGetSymbolAddress((void**)&vT, g_vT);
    cudaGetSymbolAddress((void**)&wqT, g_wqT);
    cudaGetSymbolAddress((void**)&wkT, g_wkT);
    cudaGetSymbolAddress((void**)&wvT, g_wvT);

    cudaFuncSetAttribute(mma_gemm<1>, cudaFuncAttributeMaxDynamicSharedMemorySize, SMEM_SZ);
    cudaFuncSetAttribute(mma_gemm<2>, cudaFuncAttributeMaxDynamicSharedMemorySize, SMEM_SZ);
    cudaFuncSetAttribute(attn_fused,  cudaFuncAttributeMaxDynamicSharedMemorySize, A_SMEM);

    // 1) fused context + query fp16 conversion; weight transposes
    ctx_qry_kernel<<<BPD / 2 / 256, 256>>>(query, aw, qry16, ctx16);
    split_wT_kernel<<<1024, 256>>>(qw, wqT);
    split_wT_kernel<<<1024, 256>>>(kw, wkT);
    split_wT_kernel<<<1024, 256>>>(vw, wvT);

    const float qscale = 0.0625f;  // D^-1/2

    // 2) q = relu(query@Wq + bq) * qscale -> fp16
    {
        dim3 g(D_ / 128, P_ / 128, Z_);
        mma_gemm<1><<<g, 256, SMEM_SZ>>>(qry16, wqT, qb, qB, P_, D_, D_, 15, qscale);
    }
    // 3) k = relu(ctx@Wk + bk) -> fp16
    {
        dim3 g(D_ / 128, P_ / 128, Z_);
        mma_gemm<1><<<g, 256, SMEM_SZ>>>(ctx16, wkT, kb, kB, P_, D_, D_, 15, 1.0f);
    }
    // 4) v = relu(ctx@Wv + bv) -> fp16 transposed [z][e][q]
    {
        dim3 g(D_ / 128, P_ / 128, Z_);
        mma_gemm<2><<<g, 256, SMEM_SZ>>>(ctx16, wvT, vb, vT, P_, D_, D_, 15, 1.0f);
    }
    // 5) fused attention: out = softmax(q k^T) v
    {
        dim3 g(P_ / 128, Z_);
        attn_fused<<<g, 256, A_SMEM>>>(qB, kB, vT, out);
    }
}

// round 8
// speedup vs baseline: 1.0248x; 1.0248x over previous
#include <cuda_runtime.h>
#include <cuda_fp16.h>
#include <cstdint>
#include <math.h>

// ---------------------------------------------------------------- dims
#define B_  16
#define C_  16
#define P_  512
#define D_  256
#define Z_  (B_*C_)            // 256 batches
#define BCPD (B_*C_*P_*D_)     // 33,554,432
#define BPD  (B_*P_*D_)        // 2,097,152
#define WELEM (C_*D_*D_)       // 1,048,576

// ---------------------------------------------------------------- scratch
__device__ half g_qry[BCPD];
__device__ half g_ctx[BCPD];
__device__ half g_q[BCPD];
__device__ half g_k[BCPD];
__device__ half g_vT[BCPD];          // blocked: [z][kv/64][e][kv%64]
__device__ half g_wqT[WELEM], g_wkT[WELEM], g_wvT[WELEM];

// ---------------------------------------------------------------- helpers
__device__ __forceinline__ uint32_t smem_u32(const void* p) {
    uint32_t a;
    asm("{ .reg .u64 t; cvta.to.shared.u64 t, %1; cvt.u32.u64 %0, t; }" : "=r"(a) : "l"(p));
    return a;
}

#define CP16(saddr, gaddr) \
    asm volatile("cp.async.cg.shared.global [%0], [%1], 16;" :: "r"(saddr), "l"(gaddr) : "memory")
#define CP_COMMIT() asm volatile("cp.async.commit_group;" ::: "memory")
#define CP_WAIT1()  asm volatile("cp.async.wait_group 1;" ::: "memory")
#define CP_WAIT0()  asm volatile("cp.async.wait_group 0;" ::: "memory")

#define LDSM4(r0, r1, r2, r3, addr) \
    asm volatile("ldmatrix.sync.aligned.m8n8.x4.shared.b16 {%0,%1,%2,%3}, [%4];" \
        : "=r"(r0), "=r"(r1), "=r"(r2), "=r"(r3) : "r"(addr))

#define MMAH(c, a, b) \
    asm volatile("mma.sync.aligned.m16n8k16.row.col.f32.f16.f16.f32 " \
        "{%0,%1,%2,%3}, {%4,%5,%6,%7}, {%8,%9}, {%0,%1,%2,%3};" \
        : "+f"((c)[0]), "+f"((c)[1]), "+f"((c)[2]), "+f"((c)[3]) \
        : "r"((a)[0]), "r"((a)[1]), "r"((a)[2]), "r"((a)[3]), "r"((b)[0]), "r"((b)[1]))

__device__ __forceinline__ uint32_t packh2(float lo, float hi) {
    __half2 h = __floats2half2_rn(lo, hi);
    return *reinterpret_cast<uint32_t*>(&h);
}

// ---------------------------------------------------------------- proj GEMM
// One launch for all three projections. z = idx*256 + zz; idx 0=q,1=k,2=v.
// D = A @ W^T + b, relu, (scale) -> fp16.  idx 0/1: Out[z][p][e];
// idx 2: vT blocked Out[z][kv/64][e][kv%64].
#define OFF_A    0
#define OFF_B    16384
#define STAGE_SZ 32768
#define SMEM_SZ  66560
#define STG_LD   130

__global__ __launch_bounds__(256, 2)
void proj_gemm(const half* __restrict__ Aq, const half* __restrict__ Actx,
               const half* __restrict__ Wq, const half* __restrict__ Wk,
               const half* __restrict__ Wv,
               const float* __restrict__ bq, const float* __restrict__ bk,
               const float* __restrict__ bv,
               half* __restrict__ Oq, half* __restrict__ Ok,
               half* __restrict__ Ov)
{
    extern __shared__ char smem[];
    const uint32_t sb = smem_u32(smem);

    const int t    = threadIdx.x;
    const int wid  = t >> 5;
    const int lane = t & 31;
    const int wr   = wid >> 2;
    const int wc   = wid & 3;

    const int zfull = blockIdx.z;
    const int idx = zfull >> 8;          // 0=q, 1=k, 2=v
    const int zz  = zfull & 255;
    const int bz  = zz & 15;             // cycle
    const int m0 = blockIdx.y * 128;
    const int n0 = blockIdx.x * 128;

    const int M = P_, N = D_, K = D_;
    const long Kb = (long)K * 2;
    const half* Abase = (idx == 0) ? Aq : Actx;
    const half* Wbase = (idx == 0) ? Wq : (idx == 1) ? Wk : Wv;
    const float* bias = (idx == 0) ? bq : (idx == 1) ? bk : bv;
    const float scale = (idx == 0) ? 0.0625f : 1.0f;

    const char* gA = (const char*)(Abase + ((long)zz * M + m0) * K);
    const char* gB = (const char*)(Wbase + ((long)bz * N + n0) * K);

    uint32_t soffv[4]; long goffv[4];
#pragma unroll
    for (int i = 0; i < 4; i++) {
        int id = t + i * 256;
        int r = id >> 3, c = id & 7;
        soffv[i] = r * 128 + ((uint32_t)(c ^ (r & 7)) << 4);
        goffv[i] = (long)r * Kb + c * 16;
    }

    uint32_t roA[4]; int swA[4];
#pragma unroll
    for (int mi = 0; mi < 4; mi++) {
        int row = wr * 64 + mi * 16 + (lane & 15);
        roA[mi] = row * 128;
        swA[mi] = row & 7;
    }
    const int a_kc = lane >> 4;
    uint32_t roB[2]; int swB[2];
#pragma unroll
    for (int nj = 0; nj < 2; nj++) {
        int row = wc * 32 + nj * 16 + (lane & 7) + ((lane >> 4) << 3);
        roB[nj] = row * 128;
        swB[nj] = row & 7;
    }
    const int b_kc = (lane >> 3) & 1;

    float acc[4][4][4];
#pragma unroll
    for (int mi = 0; mi < 4; mi++)
#pragma unroll
        for (int ni = 0; ni < 4; ni++)
#pragma unroll
            for (int r = 0; r < 4; r++) acc[mi][ni][r] = 0.f;

    auto load_chunk = [&](int ch, int buf) {
        const uint32_t s = sb + buf * STAGE_SZ;
        const long gk = (long)ch * 128;
#pragma unroll
        for (int i = 0; i < 4; i++) {
            CP16(s + OFF_A + soffv[i], gA + goffv[i] + gk);
            CP16(s + OFF_B + soffv[i], gB + goffv[i] + gk);
        }
        CP_COMMIT();
    };

    load_chunk(0, 0);

    const int nch = K >> 6;
    for (int ch = 0; ch < nch; ch++) {
        const int buf = ch & 1;
        if (ch + 1 < nch) { load_chunk(ch + 1, (ch + 1) & 1); CP_WAIT1(); }
        else              { CP_WAIT0(); }
        __syncthreads();

        const uint32_t sA = sb + buf * STAGE_SZ + OFF_A;
        const uint32_t sB = sb + buf * STAGE_SZ + OFF_B;

#pragma unroll
        for (int ks = 0; ks < 4; ks++) {
            const int kcA = ks * 2 + a_kc;
            const int kcB = ks * 2 + b_kc;

            uint32_t a[4][4], b[4][2];
#pragma unroll
            for (int mi = 0; mi < 4; mi++)
                LDSM4(a[mi][0], a[mi][1], a[mi][2], a[mi][3],
                      sA + roA[mi] + ((uint32_t)(kcA ^ swA[mi]) << 4));
#pragma unroll
            for (int nj = 0; nj < 2; nj++)
                LDSM4(b[nj*2][0], b[nj*2][1], b[nj*2+1][0], b[nj*2+1][1],
                      sB + roB[nj] + ((uint32_t)(kcB ^ swB[nj]) << 4));
#pragma unroll
            for (int mi = 0; mi < 4; mi++)
#pragma unroll
                for (int ni = 0; ni < 4; ni++)
                    MMAH(acc[mi][ni], a[mi], b[ni]);
        }
        __syncthreads();
    }

    // epilogue via padded smem stage
    float* stg = reinterpret_cast<float*>(smem);
    {
        const int grp = lane >> 2;
        const int tq  = lane & 3;
#pragma unroll
        for (int mi = 0; mi < 4; mi++) {
            const int m = wr * 64 + mi * 16 + grp;
#pragma unroll
            for (int ni = 0; ni < 4; ni++) {
                const int n = wc * 32 + ni * 8 + 2 * tq;
                stg[m * STG_LD + n]           = acc[mi][ni][0];
                stg[m * STG_LD + n + 1]       = acc[mi][ni][1];
                stg[(m + 8) * STG_LD + n]     = acc[mi][ni][2];
                stg[(m + 8) * STG_LD + n + 1] = acc[mi][ni][3];
            }
        }
    }
    __syncthreads();

    const float* brow = bias + (long)bz * N + n0;

    if (idx < 2) {
        half* OutH = (idx == 0) ? Oq : Ok;
#pragma unroll
        for (int r = 0; r < 32; r++) {
            int id = r * 256 + t;
            int m = id >> 6, j = id & 63;
            int n = 2 * j;
            float v0 = fmaxf(stg[m * STG_LD + n]     + brow[n],     0.f) * scale;
            float v1 = fmaxf(stg[m * STG_LD + n + 1] + brow[n + 1], 0.f) * scale;
            long base = ((long)zz * M + m0 + m) * N + n0 + n;
            __half2 H; H.x = __float2half(v0); H.y = __float2half(v1);
            *reinterpret_cast<__half2*>(&OutH[base]) = H;
        }
    } else {
        // vT blocked: Ov[zz][kv>>6][e][kv&63], e = n0+row, kv = m0+col
#pragma unroll
        for (int r = 0; r < 32; r++) {
            int id = r * 256 + t;
            int e = id >> 6, j = id & 63;
            int q = 2 * j;
            float bv2 = brow[e];
            float v0 = fmaxf(stg[q * STG_LD + e]       + bv2, 0.f);
            float v1 = fmaxf(stg[(q + 1) * STG_LD + e] + bv2, 0.f);
            int kv = m0 + q;
            long base = (long)zz * (D_ * P_) + (long)(kv >> 6) * (D_ * 64)
                      + (long)(n0 + e) * 64 + (kv & 63);
            __half2 H; H.x = __float2half(v0); H.y = __float2half(v1);
            *reinterpret_cast<__half2*>(&Ov[base]) = H;
        }
    }
}

// ---------------------------------------------------------------- fused attention
// out[z][p][e] = softmax_kv( q . k ) @ v, v given blocked vT[z][j][e][64].
// CTA: 256 thr / 8 warps; q-block 128 (16 rows/warp), kv-block 64, 8 iters;
// online softmax; P stays in registers as A-frags.
#define A_OFQ   0
#define A_OFK0  65536
#define A_OFK1  98304
#define A_OFV0  131072
#define A_OFV1  163840
#define A_SMEM  196608

__global__ __launch_bounds__(256, 1)
void attn_fused(const half* __restrict__ Qm, const half* __restrict__ Km,
                const half* __restrict__ Vtm, float* __restrict__ Out)
{
    extern __shared__ char smem[];
    const uint32_t sb = smem_u32(smem);
    const int t = threadIdx.x;
    const int wid = t >> 5, lane = t & 31;
    const int z  = blockIdx.y;
    const int p0 = blockIdx.x * 128;

    const char* gQ = (const char*)(Qm  + ((long)z * P_ + p0) * D_);
    const char* gK = (const char*)(Km  + (long)z * P_ * D_);
    const char* gV = (const char*)(Vtm + (long)z * D_ * P_);

    // Q: 128 rows x 512B, swizzle (r&7)<<2 on 16B chunks
#pragma unroll
    for (int i = 0; i < 16; i++) {
        int id = t + i * 256;
        int r = id >> 5, c = id & 31;
        CP16(sb + A_OFQ + r * 512 + ((uint32_t)(c ^ ((r & 7) << 2)) << 4),
             gQ + (long)r * 512 + c * 16);
    }
    auto loadK = [&](int j, uint32_t dst) {     // 64 rows x 512B contiguous
#pragma unroll
        for (int i = 0; i < 8; i++) {
            int id = t + i * 256;
            int r = id >> 5, c = id & 31;
            CP16(dst + r * 512 + ((uint32_t)(c ^ ((r & 7) << 2)) << 4),
                 gK + ((long)(j * 64 + r)) * 512 + c * 16);
        }
    };
    auto loadV = [&](int j, uint32_t dst) {     // blocked: 32KB contiguous
#pragma unroll
        for (int i = 0; i < 8; i++) {
            int id = t + i * 256;
            int r = id >> 3, c = id & 7;
            CP16(dst + r * 128 + ((uint32_t)(c ^ (r & 7)) << 4),
                 gV + (long)j * 32768 + (long)id * 16);
        }
    };
    loadK(0, sb + A_OFK0);
    loadV(0, sb + A_OFV0);
    CP_COMMIT();

    const int grp = lane >> 2, tq = lane & 3;
    const int aRow = wid * 16 + (lane & 15);
    const uint32_t aRO = aRow * 512;
    const uint32_t aSW = (uint32_t)(aRow & 7) << 2;
    const int a_kc = lane >> 4;
    const int bRowB = (lane & 7) + ((lane >> 4) << 3);
    const int b_kc  = (lane >> 3) & 1;
    const uint32_t vSW = (uint32_t)(lane & 7);

    float accO[32][4];
#pragma unroll
    for (int ni = 0; ni < 32; ni++)
#pragma unroll
        for (int r = 0; r < 4; r++) accO[ni][r] = 0.f;
    float mrow0 = -1e30f, mrow1 = -1e30f, lrow0 = 0.f, lrow1 = 0.f;

    for (int j = 0; j < 8; j++) {
        const uint32_t sK = sb + ((j & 1) ? A_OFK1 : A_OFK0);
        const uint32_t sV = sb + ((j & 1) ? A_OFV1 : A_OFV0);
        if (j < 7) {
            loadK(j + 1, sb + (((j + 1) & 1) ? A_OFK1 : A_OFK0));
            loadV(j + 1, sb + (((j + 1) & 1) ? A_OFV1 : A_OFV0));
            CP_COMMIT();
            CP_WAIT1();
        } else {
            CP_WAIT0();
        }
        __syncthreads();

        // ---- S = Q @ K_j^T : warp tile 16 x 64
        float accS[8][4];
#pragma unroll
        for (int ni = 0; ni < 8; ni++)
#pragma unroll
            for (int r = 0; r < 4; r++) accS[ni][r] = 0.f;

#pragma unroll
        for (int ks = 0; ks < 16; ks++) {
            uint32_t a[4];
            LDSM4(a[0], a[1], a[2], a[3],
                  sb + A_OFQ + aRO + ((uint32_t)((ks * 2 + a_kc) ^ aSW) << 4));
#pragma unroll
            for (int nj = 0; nj < 4; nj++) {
                uint32_t bf[4];
                int n = nj * 16 + bRowB;
                LDSM4(bf[0], bf[1], bf[2], bf[3],
                      sK + n * 512 + ((uint32_t)((ks * 2 + b_kc) ^ ((n & 7) << 2)) << 4));
                MMAH(accS[2 * nj],     a, (&bf[0]));
                MMAH(accS[2 * nj + 1], a, (&bf[2]));
            }
        }

        // ---- online softmax (rows grp and grp+8 of this warp's 16)
        float rmax0 = -1e30f, rmax1 = -1e30f;
#pragma unroll
        for (int ni = 0; ni < 8; ni++) {
            rmax0 = fmaxf(rmax0, fmaxf(accS[ni][0], accS[ni][1]));
            rmax1 = fmaxf(rmax1, fmaxf(accS[ni][2], accS[ni][3]));
        }
        rmax0 = fmaxf(rmax0, __shfl_xor_sync(0xffffffffu, rmax0, 1));
        rmax0 = fmaxf(rmax0, __shfl_xor_sync(0xffffffffu, rmax0, 2));
        rmax1 = fmaxf(rmax1, __shfl_xor_sync(0xffffffffu, rmax1, 1));
        rmax1 = fmaxf(rmax1, __shfl_xor_sync(0xffffffffu, rmax1, 2));

        const float mn0 = fmaxf(mrow0, rmax0);
        const float mn1 = fmaxf(mrow1, rmax1);
        const float sc0 = __expf(mrow0 - mn0);
        const float sc1 = __expf(mrow1 - mn1);
        mrow0 = mn0; mrow1 = mn1;

        float rs0 = 0.f, rs1 = 0.f;
#pragma unroll
        for (int ni = 0; ni < 8; ni++) {
            accS[ni][0] = __expf(accS[ni][0] - mn0);
            accS[ni][1] = __expf(accS[ni][1] - mn0);
            accS[ni][2] = __expf(accS[ni][2] - mn1);
            accS[ni][3] = __expf(accS[ni][3] - mn1);
            rs0 += accS[ni][0] + accS[ni][1];
            rs1 += accS[ni][2] + accS[ni][3];
        }
        rs0 += __shfl_xor_sync(0xffffffffu, rs0, 1);
        rs0 += __shfl_xor_sync(0xffffffffu, rs0, 2);
        rs1 += __shfl_xor_sync(0xffffffffu, rs1, 1);
        rs1 += __shfl_xor_sync(0xffffffffu, rs1, 2);
        lrow0 = lrow0 * sc0 + rs0;
        lrow1 = lrow1 * sc1 + rs1;

#pragma unroll
        for (int ni = 0; ni < 32; ni++) {
            accO[ni][0] *= sc0; accO[ni][1] *= sc0;
            accO[ni][2] *= sc1; accO[ni][3] *= sc1;
        }

        // P as A-fragments (C-frag layout == A-frag layout)
        uint32_t pa[4][4];
#pragma unroll
        for (int kk = 0; kk < 4; kk++) {
            pa[kk][0] = packh2(accS[2 * kk][0],     accS[2 * kk][1]);
            pa[kk][1] = packh2(accS[2 * kk][2],     accS[2 * kk][3]);
            pa[kk][2] = packh2(accS[2 * kk + 1][0], accS[2 * kk + 1][1]);
            pa[kk][3] = packh2(accS[2 * kk + 1][2], accS[2 * kk + 1][3]);
        }

        // ---- O += P @ V_j : warp tile 16 x 256 (per-kk b loads)
#pragma unroll
        for (int ng = 0; ng < 8; ng++) {
            const int n1 = ng * 32 + bRowB;
            const int n2 = n1 + 16;
#pragma unroll
            for (int kk = 0; kk < 4; kk++) {
                uint32_t bb[8];
                const uint32_t kc = (uint32_t)(kk * 2 + b_kc);
                LDSM4(bb[0], bb[1], bb[2], bb[3], sV + n1 * 128 + ((kc ^ vSW) << 4));
                LDSM4(bb[4], bb[5], bb[6], bb[7], sV + n2 * 128 + ((kc ^ vSW) << 4));
                MMAH(accO[ng * 4 + 0], pa[kk], (&bb[0]));
                MMAH(accO[ng * 4 + 1], pa[kk], (&bb[2]));
                MMAH(accO[ng * 4 + 2], pa[kk], (&bb[4]));
                MMAH(accO[ng * 4 + 3], pa[kk], (&bb[6]));
            }
        }
        __syncthreads();
    }

    // ---- epilogue: normalize and store fp32
    const float inv0 = 1.f / lrow0;
    const float inv1 = 1.f / lrow1;
    const int rowp = p0 + wid * 16 + grp;
    const long base0 = ((long)z * P_ + rowp) * D_;
    const long base1 = base0 + 8 * D_;
#pragma unroll
    for (int ni = 0; ni < 32; ni++) {
        const int col = ni * 8 + 2 * tq;
        float2 v0; v0.x = accO[ni][0] * inv0; v0.y = accO[ni][1] * inv0;
        float2 v1; v1.x = accO[ni][2] * inv1; v1.y = accO[ni][3] * inv1;
        *reinterpret_cast<float2*>(&Out[base0 + col]) = v0;
        *reinterpret_cast<float2*>(&Out[base1 + col]) = v1;
    }
}

// ---------------------------------------------------------------- elementwise
__global__ __launch_bounds__(256) void ctx_qry_kernel(
        const float* __restrict__ q, const float* __restrict__ aw,
        half* __restrict__ qry16, half* __restrict__ ctx16)
{
    int idx = blockIdx.x * 256 + threadIdx.x;      // over BPD/2
    if (idx >= BPD / 2) return;
    int dp = idx & 127;
    int p  = (idx >> 7) & 511;
    int b  = idx >> 16;

    float2 qv[C_], pr[C_];
    float2 accv = make_float2(0.f, 0.f);
#pragma unroll
    for (int c = 0; c < C_; c++) {
        long qo = ((long)((b * C_ + c) * P_ + p)) * D_ + 2 * dp;
        long ao = ((long)(c * P_ + p)) * D_ + 2 * dp;
        float2 qq = *reinterpret_cast<const float2*>(&q[qo]);
        float2 w  = *reinterpret_cast<const float2*>(&aw[ao]);
        qv[c] = qq;
        pr[c].x = w.x * qq.x; pr[c].y = w.y * qq.y;
        accv.x += pr[c].x;    accv.y += pr[c].y;
    }
#pragma unroll
    for (int c = 0; c < C_; c++) {
        long o = ((long)((b * C_ + c) * P_ + p)) * D_ + 2 * dp;
        __half2 Cv; Cv.x = __float2half(accv.x - pr[c].x);
        Cv.y = __float2half(accv.y - pr[c].y);
        *reinterpret_cast<__half2*>(&ctx16[o]) = Cv;
        __half2 Qv; Qv.x = __float2half(qv[c].x);
        Qv.y = __float2half(qv[c].y);
        *reinterpret_cast<__half2*>(&qry16[o]) = Qv;
    }
}

__global__ __launch_bounds__(256) void split_wT_kernel(const float* __restrict__ w,
                                                       half* __restrict__ wT)
{
    __shared__ float s[32][33];
    int bc = blockIdx.x >> 6;
    int t6 = blockIdx.x & 63;
    int e0 = (t6 >> 3) * 32, d0 = (t6 & 7) * 32;
    int tx = threadIdx.x & 31, ty = threadIdx.x >> 5;
#pragma unroll
    for (int r = 0; r < 4; r++) {
        int row = ty + r * 8;
        s[row][tx] = w[((long)bc * 256 + d0 + row) * 256 + e0 + tx];
    }
    __syncthreads();
#pragma unroll
    for (int r = 0; r < 4; r++) {
        int row = ty + r * 8;
        wT[((long)bc * 256 + e0 + row) * 256 + d0 + tx] = __float2half(s[tx][row]);
    }
}

// ---------------------------------------------------------------- launcher
extern "C" void kernel_launch(void* const* d_in, const int* in_sizes, int n_in,
                              void* d_out, int out_size)
{
    const float* query = (const float*)d_in[0];
    const float* aw    = (const float*)d_in[1];
    const float* qw    = (const float*)d_in[2];
    const float* kw    = (const float*)d_in[3];
    const float* vw    = (const float*)d_in[4];
    const float* qb    = (const float*)d_in[5];
    const float* kb    = (const float*)d_in[6];
    const float* vb    = (const float*)d_in[7];
    float* out = (float*)d_out;

    half *qry16, *ctx16, *qB, *kB, *vT;
    half *wqT, *wkT, *wvT;
    cudaGetSymbolAddress((void**)&qry16, g_qry);
    cudaGetSymbolAddress((void**)&ctx16, g_ctx);
    cudaGetSymbolAddress((void**)&qB, g_q);
    cudaGetSymbolAddress((void**)&kB, g_k);
    cudaGetSymbolAddress((void**)&vT, g_vT);
    cudaGetSymbolAddress((void**)&wqT, g_wqT);
    cudaGetSymbolAddress((void**)&wkT, g_wkT);
    cudaGetSymbolAddress((void**)&wvT, g_wvT);

    cudaFuncSetAttribute(proj_gemm,  cudaFuncAttributeMaxDynamicSharedMemorySize, SMEM_SZ);
    cudaFuncSetAttribute(attn_fused, cudaFuncAttributeMaxDynamicSharedMemorySize, A_SMEM);

    // 1) fused context + query fp16 conversion; weight transposes
    ctx_qry_kernel<<<BPD / 2 / 256, 256>>>(query, aw, qry16, ctx16);
    split_wT_kernel<<<1024, 256>>>(qw, wqT);
    split_wT_kernel<<<1024, 256>>>(kw, wkT);
    split_wT_kernel<<<1024, 256>>>(vw, wvT);

    // 2) all three projections in one launch
    {
        dim3 g(D_ / 128, P_ / 128, 3 * Z_);
        proj_gemm<<<g, 256, SMEM_SZ>>>(qry16, ctx16, wqT, wkT, wvT,
                                       qb, kb, vb, qB, kB, vT);
    }
    // 3) fused attention: out = softmax(q k^T) v
    {
        dim3 g(P_ / 128, Z_);
        attn_fused<<<g, 256, A_SMEM>>>(qB, kB, vT, out);
    }
}